// round 1
// baseline (speedup 1.0000x reference)
#include <cuda_runtime.h>

// Haar level-1 high-pass: out = x - mean(2x2 block), x shape (8, 64, 512, 512) fp32.
// Flattened view: rows of length W=512, total rows R = 8*64*512 = 262144.
// Each thread: one row-pair (2r, 2r+1) x 4 columns => two float4 loads, two float4 stores.

static constexpr int W      = 512;
static constexpr int W4     = W / 4;          // 128 float4 per row
static constexpr int ROWS   = 8 * 64 * 512;   // 262144 rows
static constexpr int NUNITS = (ROWS / 2) * W4; // 16,777,216 thread-units

__global__ void __launch_bounds__(256) fastwt_high_kernel(
    const float4* __restrict__ in, float4* __restrict__ out)
{
    int idx = blockIdx.x * blockDim.x + threadIdx.x;   // < NUNITS (exact grid)
    int cw      = idx & (W4 - 1);     // column group 0..127
    int rowpair = idx >> 7;           // idx / 128

    int i0 = rowpair * (2 * W4) + cw; // float4 index, row 2r
    int i1 = i0 + W4;                 // row 2r+1

    float4 a = in[i0];
    float4 b = in[i1];

    float m0 = (a.x + a.y + b.x + b.y) * 0.25f;
    float m1 = (a.z + a.w + b.z + b.w) * 0.25f;

    float4 o0 = make_float4(a.x - m0, a.y - m0, a.z - m1, a.w - m1);
    float4 o1 = make_float4(b.x - m0, b.y - m0, b.z - m1, b.w - m1);

    out[i0] = o0;
    out[i1] = o1;
}

extern "C" void kernel_launch(void* const* d_in, const int* in_sizes, int n_in,
                              void* d_out, int out_size)
{
    const float4* in  = (const float4*)d_in[0];
    float4*       out = (float4*)d_out;
    constexpr int TPB = 256;
    fastwt_high_kernel<<<NUNITS / TPB, TPB>>>(in, out);
}